// round 16
// baseline (speedup 1.0000x reference)
#include <cuda_runtime.h>
#include <cuda_bf16.h>

#define BB 8
#define HH 128
typedef unsigned int u32;

// fp32 workspaces (ground truth) + bf16 hi/lo planes (MMA operands)
__device__ float g_ws1[(size_t)BB*128*128*128];
__device__ float g_ws2[(size_t)BB*128*128*128];
__device__ __align__(256) __nv_bfloat16 g_p1h[(size_t)BB*128*128*128];
__device__ __align__(256) __nv_bfloat16 g_p1l[(size_t)BB*128*128*128];
__device__ __align__(256) __nv_bfloat16 g_p2h[(size_t)BB*128*128*128];
__device__ __align__(256) __nv_bfloat16 g_p2l[(size_t)BB*128*128*128];
// Split weights, ORIGINAL layout [dir*9+kw][ic][oc]
__device__ __align__(256) __nv_bfloat16 g_wh[(size_t)36*128*128];
__device__ __align__(256) __nv_bfloat16 g_wl[(size_t)36*128*128];
// Row-completion flags: [scan(4)][b(8)][row(128)][pt(4)], 4 increments each
__device__ u32 g_cnt[4*8*128*4];

// ---------------- helpers ----------------
__device__ __forceinline__ u32 smem_u32(const void* p){
    u32 a; asm("{ .reg .u64 t; cvta.to.shared.u64 t, %1; cvt.u32.u64 %0, t; }":"=r"(a):"l"(p)); return a;
}
__device__ __forceinline__ void cpa16cg(u32 d, const void* g){
    asm volatile("cp.async.cg.shared.global [%0],[%1],16;\n"::"r"(d),"l"(g):"memory");
}
__device__ __forceinline__ void cpa16(u32 d, const void* g){
    asm volatile("cp.async.ca.shared.global [%0],[%1],16;\n"::"r"(d),"l"(g):"memory");
}
__device__ __forceinline__ void sts16z(u32 d){
    asm volatile("st.shared.v4.b32 [%0],{%1,%1,%1,%1};\n"::"r"(d),"r"(0):"memory");
}
__device__ __forceinline__ void ldsm4(u32* a, u32 addr){
    asm volatile("ldmatrix.sync.aligned.m8n8.x4.shared.b16 {%0,%1,%2,%3},[%4];"
        :"=r"(a[0]),"=r"(a[1]),"=r"(a[2]),"=r"(a[3]):"r"(addr));
}
__device__ __forceinline__ void ldsm4t(u32* b, u32 addr){
    asm volatile("ldmatrix.sync.aligned.m8n8.x4.trans.shared.b16 {%0,%1,%2,%3},[%4];"
        :"=r"(b[0]),"=r"(b[1]),"=r"(b[2]),"=r"(b[3]):"r"(addr));
}
__device__ __forceinline__ void mma16816(float* c,const u32* a,u32 b0,u32 b1){
    asm volatile("mma.sync.aligned.m16n8k16.row.col.f32.bf16.bf16.f32 "
        "{%0,%1,%2,%3},{%4,%5,%6,%7},{%8,%9},{%0,%1,%2,%3};"
        :"+f"(c[0]),"+f"(c[1]),"+f"(c[2]),"+f"(c[3])
        :"r"(a[0]),"r"(a[1]),"r"(a[2]),"r"(a[3]),"r"(b0),"r"(b1));
}
__device__ __forceinline__ u32 ld_acquire(const u32* p){
    u32 v;
    asm volatile("ld.acquire.gpu.global.b32 %0,[%1];" : "=r"(v) : "l"(p) : "memory");
    return v;
}
__device__ __forceinline__ void red_release_add(u32* p, u32 v){
    asm volatile("red.release.gpu.global.add.u32 [%0],%1;" :: "l"(p), "r"(v) : "memory");
}

// smem layout (dynamic, 220416 B, opt-in):
//   A : 2 planes x 40 rows x 272B        @ 0       (plane stride 10880)
//   W : 9 kw x 128 ic x 144B packed rows @ 21760   ([32oc hi][32oc lo] per row)
//   Rm: 8 slices x 1024 f32 partials     @ 187648  (dedicated, no aliasing)
#define SM_A1   10880
#define SM_W    21760
#define SM_WKW  18432
#define SM_RM   187648
#define SMEM_BYTES 220416

// ---------------------------------------------------------------------------
// Persistent directional scan: 128 blocks (4 pt x 4 ot x 8 b) = one wave.
// 512 threads = 16 warps. Warp = (h = wid>>3 : kw-half {0-4 | 5-8}) x
// (s = wid&7 : 16-ic slice). Each warp covers the full 32pos x 32oc tile
// over its (ic-slice, kw-half). Two-hop reduction through dedicated Rm.
// ---------------------------------------------------------------------------
template<int WS>
__global__ __launch_bounds__(512) void scan_kernel(int dir, int rev, int scan_idx)
{
    extern __shared__ __align__(1024) char smem[];
    const u32 sb = smem_u32(smem);
    const int tid = threadIdx.x, wid = tid>>5, lane = tid&31;
    const int h = wid>>3, s = wid&7;
    const int ic0 = s*16;
    const int pt = blockIdx.x;
    const int p0 = pt*32, oc0 = blockIdx.y*32, b = blockIdx.z;

    float* yw = WS? g_ws2 : g_ws1;
    __nv_bfloat16* ph = WS? g_p2h : g_p1h;
    __nv_bfloat16* pl = WS? g_p2l : g_p1l;
    const __nv_bfloat16* Wh = g_wh + (size_t)dir*9*16384;
    const __nv_bfloat16* Wl = g_wl + (size_t)dir*9*16384;
    u32* cntrow = g_cnt + (size_t)((scan_idx*8 + b)*128)*4;

    // ---- Stage ALL weights once: packed rows [32oc hi | 32oc lo], 144B stride ----
    for (int t = tid; t < 9216; t += 512){
        int kw = t >> 10, rem = t & 1023;
        int pi = rem >> 9, ic = (rem >> 2) & 127, j = rem & 3;
        u32 dst = sb + SM_W + kw*SM_WKW + ic*144 + pi*64 + j*16;
        cpa16(dst, (pi? Wl : Wh) + (size_t)kw*16384 + (size_t)ic*128 + oc0 + j*8);
    }
    asm volatile("cp.async.commit_group;\n":::"memory");
    asm volatile("cp.async.wait_group 0;\n":::"memory");
    __syncthreads();

    const int ar = lane & 15, ac = (lane>>4)*16;
    const u32 A0 = sb, A1 = sb + SM_A1;
    // B fragment address within a kw slice (rows 144B; hi @ +0/+32, lo @ +64/+96)
    const u32 baddr = (u32)(ic0 + (lane&15))*144 + (u32)((lane>>4)*16);
    // Epilogue mapping: thread owns (pos = tid>>4, oc pair = (tid&15)*2)
    const int ep_pos = tid >> 4;           // 0..31
    const int ep_oc  = (tid & 15)*2;       // even oc
    const int g_m  = ep_pos >> 4;
    const int g_n  = ep_oc >> 3;
    const int g_q0 = ((ep_pos >> 3) & 1)*2;
    const int g_ln = ((ep_pos & 7) << 2) | ((ep_oc >> 1) & 3);
    const int g_off0 = (g_m*16 + g_n*4 + g_q0)*32 + g_ln;
    const int g_off1 = g_off0 + 32;        // q0+1

    for (int i = 1; i < 128; ++i){
        const int row  = rev ? 127 - i : i;
        const int prev = rev ? row + 1 : row - 1;
        const size_t rowbase = ((size_t)b*128 + row)*128;
        const size_t eidx = (rowbase + p0 + ep_pos)*128 + oc0 + ep_oc;

        // Flag-independent prefetch (this block is sole writer of its tile).
        float2 ypre = *(float2*)(yw + eidx);

        // ---- Wait: flags (prev, pt-1..pt+1) >= 4 ----
        if (i > 1){
            if (tid < 3){
                int q = pt + tid - 1;
                if (q >= 0 && q < 4){
                    u32* f = cntrow + prev*4 + q;
                    while (ld_acquire(f) < 4u) { }
                }
                __threadfence();
            }
            __syncthreads();
        }

        // ---- Stage A window of prev row (L2-only cp.async.cg) ----
        const __nv_bfloat16* Ah_src = ph + ((size_t)b*128 + prev)*16384;
        const __nv_bfloat16* Al_src = pl + ((size_t)b*128 + prev)*16384;
        #pragma unroll
        for (int q = 0; q < 3; ++q){
            int idx = tid + 512*q;             // 1280 chunks of 16B
            if (idx < 1280){
                int pi  = idx >= 640;
                int rem = idx - pi*640;
                int r = rem >> 4, j = rem & 15;
                int gp = p0 - 4 + r;
                u32 dst = sb + pi*SM_A1 + r*272 + j*16;
                if (gp >= 0 && gp < 128)
                    cpa16cg(dst, (pi? Al_src : Ah_src) + (size_t)gp*128 + j*8);
                else
                    sts16z(dst);
            }
        }
        asm volatile("cp.async.commit_group;\n":::"memory");
        asm volatile("cp.async.wait_group 0;\n":::"memory");
        __syncthreads();

        // ---- Compute: warp covers 32pos x 32oc x (16ic, kw-half) ----
        float c[2][4][4];
        #pragma unroll
        for (int m = 0; m < 2; ++m)
            #pragma unroll
            for (int n = 0; n < 4; ++n)
                #pragma unroll
                for (int q = 0; q < 4; ++q) c[m][n][q] = 0.f;

        #define KW_BODY(kw) do{                                               \
            const u32 Wb = sb + SM_W + (kw)*SM_WKW;                           \
            u32 bh[8], bl[8];                                                 \
            ldsm4t(&bh[0], Wb + baddr);                                       \
            ldsm4t(&bh[4], Wb + baddr + 32);                                  \
            ldsm4t(&bl[0], Wb + baddr + 64);                                  \
            ldsm4t(&bl[4], Wb + baddr + 96);                                  \
            u32 ah[2][4], al[2][4];                                           \
            _Pragma("unroll")                                                 \
            for (int m = 0; m < 2; ++m){                                      \
                const u32 ra = (u32)((kw) + 16*m + ar)*272 + (u32)ic0*2 + ac; \
                ldsm4(ah[m], A0 + ra);                                        \
                ldsm4(al[m], A1 + ra);                                        \
            }                                                                 \
            _Pragma("unroll")                                                 \
            for (int m = 0; m < 2; ++m)                                       \
                _Pragma("unroll")                                             \
                for (int n = 0; n < 4; ++n)                                   \
                    mma16816(c[m][n], ah[m], bh[2*n], bh[2*n+1]);             \
            _Pragma("unroll")                                                 \
            for (int m = 0; m < 2; ++m)                                       \
                _Pragma("unroll")                                             \
                for (int n = 0; n < 4; ++n)                                   \
                    mma16816(c[m][n], ah[m], bl[2*n], bl[2*n+1]);             \
            _Pragma("unroll")                                                 \
            for (int m = 0; m < 2; ++m)                                       \
                _Pragma("unroll")                                             \
                for (int n = 0; n < 4; ++n)                                   \
                    mma16816(c[m][n], al[m], bh[2*n], bh[2*n+1]);             \
        }while(0)

        if (h == 0){
            KW_BODY(0); KW_BODY(1); KW_BODY(2); KW_BODY(3); KW_BODY(4);
        } else {
            KW_BODY(5); KW_BODY(6); KW_BODY(7); KW_BODY(8);
        }
        #undef KW_BODY

        // ---- Two-hop reduction through dedicated Rm (no aliasing) ----
        float* Rm = (float*)(smem + SM_RM);
        if (h == 1){
            #pragma unroll
            for (int m = 0; m < 2; ++m)
                #pragma unroll
                for (int n = 0; n < 4; ++n)
                    #pragma unroll
                    for (int q = 0; q < 4; ++q)
                        Rm[s*1024 + (m*16 + n*4 + q)*32 + lane] = c[m][n][q];
        }
        __syncthreads();
        if (h == 0){
            #pragma unroll
            for (int m = 0; m < 2; ++m)
                #pragma unroll
                for (int n = 0; n < 4; ++n)
                    #pragma unroll
                    for (int q = 0; q < 4; ++q){
                        int off = s*1024 + (m*16 + n*4 + q)*32 + lane;
                        Rm[off] = c[m][n][q] + Rm[off];
                    }
        }
        __syncthreads();

        // ---- Gather 8 slices + fused epilogue (all 512 threads) ----
        float v0, v1;
        {
            float s0 = 0.f, s1 = 0.f;
            #pragma unroll
            for (int w = 0; w < 8; ++w){
                s0 += Rm[w*1024 + g_off0];
                s1 += Rm[w*1024 + g_off1];
            }
            v0 = ypre.x + fmaxf(s0, 0.f);
            v1 = ypre.y + fmaxf(s1, 0.f);

            __nv_bfloat16 h0 = __float2bfloat16(v0), h1 = __float2bfloat16(v1);
            __nv_bfloat162 hp; hp.x = h0; hp.y = h1;
            *(__nv_bfloat162*)(ph + eidx) = hp;
            __nv_bfloat162 lp;
            lp.x = __float2bfloat16(v0 - __bfloat162float(h0));
            lp.y = __float2bfloat16(v1 - __bfloat162float(h1));
            *(__nv_bfloat162*)(pl + eidx) = lp;
        }

        // ---- Publish (planes only gate consumers); y fp32 store deferred ----
        __syncthreads();
        if (tid == 0)
            red_release_add(cntrow + row*4 + pt, 1u);
        *(float2*)(yw + eidx) = make_float2(v0, v1);
    }
}

// ---------------------------------------------------------------------------
__global__ void zero_cnt()
{
    int i = blockIdx.x*blockDim.x + threadIdx.x;
    if (i < 4*8*128*4) g_cnt[i] = 0u;
}

// Weight split prep: fp32 [kw][ic][oc] -> bf16 hi/lo, same layout, 4 dirs.
__global__ void prep_w(const float* __restrict__ k0, const float* __restrict__ k1,
                       const float* __restrict__ k2, const float* __restrict__ k3)
{
    const size_t n = (size_t)36*16384;
    for (size_t i = (size_t)blockIdx.x*blockDim.x + threadIdx.x; i < n;
         i += (size_t)gridDim.x*blockDim.x){
        int z = (int)(i >> 14), rem = (int)(i & 16383);
        const float* sp = (z < 9)? k0 : (z < 18)? k1 : (z < 27)? k2 : k3;
        float v = sp[(size_t)(z % 9)*16384 + rem];
        __nv_bfloat16 hv = __float2bfloat16(v);
        g_wh[i] = hv;
        g_wl[i] = __float2bfloat16(v - __bfloat162float(hv));
    }
}

// ---------------------------------------------------------------------------
// Transposes
// ---------------------------------------------------------------------------
__global__ void t_in(const float* __restrict__ x)
{
    __shared__ float t[32][33];
    const int bh = blockIdx.z, b = bh>>7, hh = bh&127;
    const int w0 = blockIdx.x*32, c0 = blockIdx.y*32;
    const int tx = threadIdx.x, ty = threadIdx.y;
    const float* src = x + (((size_t)b*128 + c0)*128 + hh)*128 + w0;
    #pragma unroll
    for (int i=0;i<4;++i){ int cc = ty*4+i; t[cc][tx] = src[(size_t)cc*16384 + tx]; }
    __syncthreads();
    const size_t base = (((size_t)b*128 + hh)*128 + w0)*128 + c0;
    #pragma unroll
    for (int i=0;i<4;++i){
        int w = ty*4+i;
        float v = t[tx][w];
        size_t idx = base + (size_t)w*128 + tx;
        g_ws1[idx] = v;
        __nv_bfloat16 hv = __float2bfloat16(v);
        g_p1h[idx] = hv;
        g_p1l[idx] = __float2bfloat16(v - __bfloat162float(hv));
    }
}

__global__ void t_mid()
{
    const int b = blockIdx.z, hh = blockIdx.y;
    const int w = blockIdx.x*blockDim.y + threadIdx.y;
    const int c4 = threadIdx.x;
    const size_t si = (((size_t)b*128 + hh)*128 + w)*128 + c4*4;
    const size_t di = (((size_t)b*128 + w)*128 + hh)*128 + c4*4;
    float4 v = *(const float4*)(g_ws1 + si);
    *(float4*)(g_ws2 + di) = v;
    float a[4] = {v.x, v.y, v.z, v.w};
    #pragma unroll
    for (int i=0;i<4;++i){
        __nv_bfloat16 hv = __float2bfloat16(a[i]);
        g_p2h[di+i] = hv;
        g_p2l[di+i] = __float2bfloat16(a[i] - __bfloat162float(hv));
    }
}

__global__ void t_out(float* __restrict__ out)
{
    __shared__ float t[32][33];
    const int bh = blockIdx.z, b = bh>>7, hh = bh&127;
    const int w0 = blockIdx.x*32, c0 = blockIdx.y*32;
    const int tx = threadIdx.x, ty = threadIdx.y;
    const float* src = g_ws2 + (((size_t)b*128 + w0)*128 + hh)*128 + c0;
    #pragma unroll
    for (int i=0;i<4;++i){ int w = ty*4+i; t[w][tx] = src[(size_t)w*16384 + tx]; }
    __syncthreads();
    float* d = out + (((size_t)b*128 + c0)*128 + hh)*128 + w0;
    #pragma unroll
    for (int i=0;i<4;++i){ int cc = ty*4+i; d[(size_t)cc*16384 + tx] = t[tx][cc]; }
}

// ---------------------------------------------------------------------------
extern "C" void kernel_launch(void* const* d_in, const int* in_sizes, int n_in,
                              void* d_out, int out_size)
{
    const float* x    = (const float*)d_in[0];
    const float* k_td = (const float*)d_in[1];
    const float* k_dt = (const float*)d_in[2];
    const float* k_lr = (const float*)d_in[3];
    const float* k_rl = (const float*)d_in[4];
    float* out = (float*)d_out;

    static bool attr_done = false;
    if (!attr_done){
        cudaFuncSetAttribute(scan_kernel<0>, cudaFuncAttributeMaxDynamicSharedMemorySize, SMEM_BYTES);
        cudaFuncSetAttribute(scan_kernel<1>, cudaFuncAttributeMaxDynamicSharedMemorySize, SMEM_BYTES);
        attr_done = true;
    }

    const dim3 tb(32,8), tg(4,4,BB*HH);
    const dim3 sg(4,4,BB);   // 128 blocks: one co-resident wave

    zero_cnt<<<32,512>>>();
    prep_w<<<72,256>>>(k_td, k_dt, k_lr, k_rl);
    t_in<<<tg,tb>>>(x);

    scan_kernel<0><<<sg,512,SMEM_BYTES>>>(0, 0, 0);   // top-down
    scan_kernel<0><<<sg,512,SMEM_BYTES>>>(1, 1, 1);   // bottom-up

    t_mid<<<dim3(32,128,BB), dim3(32,4)>>>();

    scan_kernel<1><<<sg,512,SMEM_BYTES>>>(2, 0, 2);   // left-right
    scan_kernel<1><<<sg,512,SMEM_BYTES>>>(3, 1, 3);   // right-left

    t_out<<<tg,tb>>>(out);
}

// round 17
// speedup vs baseline: 1.0572x; 1.0572x over previous
#include <cuda_runtime.h>
#include <cuda_bf16.h>

#define BB 8
#define HH 128
typedef unsigned int u32;

// fp32 workspaces (ground truth) + bf16 hi/lo planes (MMA operands)
__device__ float g_ws1[(size_t)BB*128*128*128];
__device__ float g_ws2[(size_t)BB*128*128*128];
__device__ __align__(256) __nv_bfloat16 g_p1h[(size_t)BB*128*128*128];
__device__ __align__(256) __nv_bfloat16 g_p1l[(size_t)BB*128*128*128];
__device__ __align__(256) __nv_bfloat16 g_p2h[(size_t)BB*128*128*128];
__device__ __align__(256) __nv_bfloat16 g_p2l[(size_t)BB*128*128*128];
// Split weights, ORIGINAL layout [dir*9+kw][ic][oc]
__device__ __align__(256) __nv_bfloat16 g_wh[(size_t)36*128*128];
__device__ __align__(256) __nv_bfloat16 g_wl[(size_t)36*128*128];
// Row-completion flags: [scan(4)][b(8)][row(128)][pt(4)], 4 increments each
__device__ u32 g_cnt[4*8*128*4];

// ---------------- helpers ----------------
__device__ __forceinline__ u32 smem_u32(const void* p){
    u32 a; asm("{ .reg .u64 t; cvta.to.shared.u64 t, %1; cvt.u32.u64 %0, t; }":"=r"(a):"l"(p)); return a;
}
__device__ __forceinline__ void cpa16cg(u32 d, const void* g){
    asm volatile("cp.async.cg.shared.global [%0],[%1],16;\n"::"r"(d),"l"(g):"memory");
}
__device__ __forceinline__ void cpa16(u32 d, const void* g){
    asm volatile("cp.async.ca.shared.global [%0],[%1],16;\n"::"r"(d),"l"(g):"memory");
}
__device__ __forceinline__ void sts16z(u32 d){
    asm volatile("st.shared.v4.b32 [%0],{%1,%1,%1,%1};\n"::"r"(d),"r"(0):"memory");
}
__device__ __forceinline__ void ldsm4(u32* a, u32 addr){
    asm volatile("ldmatrix.sync.aligned.m8n8.x4.shared.b16 {%0,%1,%2,%3},[%4];"
        :"=r"(a[0]),"=r"(a[1]),"=r"(a[2]),"=r"(a[3]):"r"(addr));
}
__device__ __forceinline__ void ldsm4t(u32* b, u32 addr){
    asm volatile("ldmatrix.sync.aligned.m8n8.x4.trans.shared.b16 {%0,%1,%2,%3},[%4];"
        :"=r"(b[0]),"=r"(b[1]),"=r"(b[2]),"=r"(b[3]):"r"(addr));
}
__device__ __forceinline__ void mma16816(float* c,const u32* a,u32 b0,u32 b1){
    asm volatile("mma.sync.aligned.m16n8k16.row.col.f32.bf16.bf16.f32 "
        "{%0,%1,%2,%3},{%4,%5,%6,%7},{%8,%9},{%0,%1,%2,%3};"
        :"+f"(c[0]),"+f"(c[1]),"+f"(c[2]),"+f"(c[3])
        :"r"(a[0]),"r"(a[1]),"r"(a[2]),"r"(a[3]),"r"(b0),"r"(b1));
}
__device__ __forceinline__ u32 ld_acquire(const u32* p){
    u32 v;
    asm volatile("ld.acquire.gpu.global.b32 %0,[%1];" : "=r"(v) : "l"(p) : "memory");
    return v;
}
__device__ __forceinline__ void red_release_add(u32* p, u32 v){
    asm volatile("red.release.gpu.global.add.u32 [%0],%1;" :: "l"(p), "r"(v) : "memory");
}

// smem layout (dynamic, 220416 B, opt-in):
//   A  : 2 planes x 40 rows x 272B        @ 0       (plane stride 10880)
//   W  : 9 kw x 128 ic x 144B packed rows @ 21760   ([32oc hi][32oc lo] per row)
//   Rm0: 8 x 512 f32 partials (m=0)       @ 187648  (dedicated, no aliasing)
//   Rm1: 8 x 512 f32 partials (m=1)       @ 204032
#define SM_A1   10880
#define SM_W    21760
#define SM_WKW  18432
#define SM_RM0  187648
#define SM_RM1  204032
#define SMEM_BYTES 220416

// ---------------------------------------------------------------------------
// Persistent directional scan: 128 blocks (4 pt x 4 ot x 8 b) = one wave.
// 256 threads = 8 warps. Warp = full 32pos x 32oc tile over ic slice
// [16*wid, 16*wid+16), all 9 kw (R15 split). Packed W rows; dedicated Rm
// (dump needs no pre-barrier). 4 barriers/step.
// ---------------------------------------------------------------------------
template<int WS>
__global__ __launch_bounds__(256) void scan_kernel(int dir, int rev, int scan_idx)
{
    extern __shared__ __align__(1024) char smem[];
    const u32 sb = smem_u32(smem);
    const int tid = threadIdx.x, wid = tid>>5, lane = tid&31;
    const int ic0 = wid*16;
    const int pt = blockIdx.x;
    const int p0 = pt*32, oc0 = blockIdx.y*32, b = blockIdx.z;

    float* yw = WS? g_ws2 : g_ws1;
    __nv_bfloat16* ph = WS? g_p2h : g_p1h;
    __nv_bfloat16* pl = WS? g_p2l : g_p1l;
    const __nv_bfloat16* Wh = g_wh + (size_t)dir*9*16384;
    const __nv_bfloat16* Wl = g_wl + (size_t)dir*9*16384;
    u32* cntrow = g_cnt + (size_t)((scan_idx*8 + b)*128)*4;

    // ---- Stage ALL weights once: packed rows [32oc hi | 32oc lo], 144B stride ----
    for (int t = tid; t < 9216; t += 256){
        int kw = t >> 10, rem = t & 1023;
        int pi = rem >> 9, ic = (rem >> 2) & 127, j = rem & 3;
        u32 dst = sb + SM_W + kw*SM_WKW + ic*144 + pi*64 + j*16;
        cpa16(dst, (pi? Wl : Wh) + (size_t)kw*16384 + (size_t)ic*128 + oc0 + j*8);
    }
    asm volatile("cp.async.commit_group;\n":::"memory");
    asm volatile("cp.async.wait_group 0;\n":::"memory");
    __syncthreads();

    const int ar = lane & 15, ac = (lane>>4)*16;
    const u32 A0 = sb, A1 = sb + SM_A1;
    // B fragment address (packed rows: hi @ +0/+32, lo @ +64/+96)
    const u32 baddr = (u32)(ic0 + (lane&15))*144 + (u32)((lane>>4)*16);
    // Epilogue mapping: thread owns (pos = tid>>4 per m-half, oc pair = (tid&15)*2)
    const int ep_p  = tid >> 4;            // 0..15 local pos within m-half
    const int ep_oc = (tid & 15)*2;        // even oc
    const int ep_n  = ep_oc >> 3;
    const int ep_q  = (ep_p >> 3)*2;
    const int ep_ln = ((ep_p & 7) << 2) | ((ep_oc >> 1) & 3);
    const int ep_off0 = (ep_n*4 + ep_q)*32 + ep_ln;
    const int ep_off1 = ep_off0 + 32;

    for (int i = 1; i < 128; ++i){
        const int row  = rev ? 127 - i : i;
        const int prev = rev ? row + 1 : row - 1;
        const size_t rowbase = ((size_t)b*128 + row)*128;
        const size_t eidx0 = (rowbase + p0 + ep_p)*128 + oc0 + ep_oc;        // m=0
        const size_t eidx1 = (rowbase + p0 + 16 + ep_p)*128 + oc0 + ep_oc;   // m=1

        // Flag-independent prefetch (this block is sole writer of its tile).
        float2 ypre0 = *(float2*)(yw + eidx0);
        float2 ypre1 = *(float2*)(yw + eidx1);

        // ---- Wait: flags (prev, pt-1..pt+1) >= 4 ----
        if (i > 1){
            if (tid < 3){
                int q = pt + tid - 1;
                if (q >= 0 && q < 4){
                    u32* f = cntrow + prev*4 + q;
                    while (ld_acquire(f) < 4u) { }
                }
                __threadfence();
            }
            __syncthreads();
        }

        // ---- Stage A window of prev row (L2-only cp.async.cg) ----
        const __nv_bfloat16* Ah_src = ph + ((size_t)b*128 + prev)*16384;
        const __nv_bfloat16* Al_src = pl + ((size_t)b*128 + prev)*16384;
        #pragma unroll
        for (int q = 0; q < 5; ++q){
            int idx = tid + 256*q;             // 1280 chunks of 16B
            int pi  = idx >= 640;
            int rem = idx - pi*640;
            int r = rem >> 4, j = rem & 15;
            int gp = p0 - 4 + r;
            u32 dst = sb + pi*SM_A1 + r*272 + j*16;
            if (gp >= 0 && gp < 128)
                cpa16cg(dst, (pi? Al_src : Ah_src) + (size_t)gp*128 + j*8);
            else
                sts16z(dst);
        }
        asm volatile("cp.async.commit_group;\n":::"memory");
        asm volatile("cp.async.wait_group 0;\n":::"memory");
        __syncthreads();

        // ---- Compute: 9 k16 chunks; warp covers 32pos x 32oc x 16ic ----
        float c[2][4][4];
        #pragma unroll
        for (int m = 0; m < 2; ++m)
            #pragma unroll
            for (int n = 0; n < 4; ++n)
                #pragma unroll
                for (int q = 0; q < 4; ++q) c[m][n][q] = 0.f;

        #pragma unroll
        for (int kw = 0; kw < 9; ++kw){
            const u32 Wb = sb + SM_W + kw*SM_WKW;
            u32 bh[8], bl[8];
            ldsm4t(&bh[0], Wb + baddr);                 // hi, oc 0-15
            ldsm4t(&bh[4], Wb + baddr + 32);            // hi, oc 16-31
            ldsm4t(&bl[0], Wb + baddr + 64);            // lo, oc 0-15
            ldsm4t(&bl[4], Wb + baddr + 96);            // lo, oc 16-31
            u32 ah[2][4], al[2][4];
            #pragma unroll
            for (int m = 0; m < 2; ++m){
                const u32 ra = (u32)(kw + 16*m + ar)*272 + (u32)ic0*2 + ac;
                ldsm4(ah[m], A0 + ra);
                ldsm4(al[m], A1 + ra);
            }
            #pragma unroll
            for (int m = 0; m < 2; ++m)
                #pragma unroll
                for (int n = 0; n < 4; ++n)
                    mma16816(c[m][n], ah[m], bh[2*n], bh[2*n+1]);
            #pragma unroll
            for (int m = 0; m < 2; ++m)
                #pragma unroll
                for (int n = 0; n < 4; ++n)
                    mma16816(c[m][n], ah[m], bl[2*n], bl[2*n+1]);
            #pragma unroll
            for (int m = 0; m < 2; ++m)
                #pragma unroll
                for (int n = 0; n < 4; ++n)
                    mma16816(c[m][n], al[m], bh[2*n], bh[2*n+1]);
        }

        // ---- Dump partials to dedicated Rm (no pre-barrier needed) ----
        float* Rm0 = (float*)(smem + SM_RM0);
        float* Rm1 = (float*)(smem + SM_RM1);
        #pragma unroll
        for (int n = 0; n < 4; ++n)
            #pragma unroll
            for (int q = 0; q < 4; ++q){
                Rm0[wid*512 + (n*4+q)*32 + lane] = c[0][n][q];
                Rm1[wid*512 + (n*4+q)*32 + lane] = c[1][n][q];
            }
        __syncthreads();

        // ---- Gather 8 partials + fused epilogue (all 256 threads) ----
        float v0, v1, v2, v3;
        {
            float s0 = 0.f, s1 = 0.f, s2 = 0.f, s3 = 0.f;
            #pragma unroll
            for (int w = 0; w < 8; ++w){
                s0 += Rm0[w*512 + ep_off0];
                s1 += Rm0[w*512 + ep_off1];
                s2 += Rm1[w*512 + ep_off0];
                s3 += Rm1[w*512 + ep_off1];
            }
            v0 = ypre0.x + fmaxf(s0, 0.f);
            v1 = ypre0.y + fmaxf(s1, 0.f);
            v2 = ypre1.x + fmaxf(s2, 0.f);
            v3 = ypre1.y + fmaxf(s3, 0.f);

            __nv_bfloat16 h0 = __float2bfloat16(v0), h1 = __float2bfloat16(v1);
            __nv_bfloat16 h2 = __float2bfloat16(v2), h3 = __float2bfloat16(v3);
            __nv_bfloat162 hp0; hp0.x = h0; hp0.y = h1;
            __nv_bfloat162 hp1; hp1.x = h2; hp1.y = h3;
            *(__nv_bfloat162*)(ph + eidx0) = hp0;
            *(__nv_bfloat162*)(ph + eidx1) = hp1;
            __nv_bfloat162 lp0, lp1;
            lp0.x = __float2bfloat16(v0 - __bfloat162float(h0));
            lp0.y = __float2bfloat16(v1 - __bfloat162float(h1));
            lp1.x = __float2bfloat16(v2 - __bfloat162float(h2));
            lp1.y = __float2bfloat16(v3 - __bfloat162float(h3));
            *(__nv_bfloat162*)(pl + eidx0) = lp0;
            *(__nv_bfloat162*)(pl + eidx1) = lp1;
        }

        // ---- Publish (planes gate consumers); fp32 y store deferred ----
        __syncthreads();
        if (tid == 0)
            red_release_add(cntrow + row*4 + pt, 1u);
        *(float2*)(yw + eidx0) = make_float2(v0, v1);
        *(float2*)(yw + eidx1) = make_float2(v2, v3);
    }
}

// ---------------------------------------------------------------------------
__global__ void zero_cnt()
{
    int i = blockIdx.x*blockDim.x + threadIdx.x;
    if (i < 4*8*128*4) g_cnt[i] = 0u;
}

// Weight split prep: fp32 [kw][ic][oc] -> bf16 hi/lo, same layout, 4 dirs.
__global__ void prep_w(const float* __restrict__ k0, const float* __restrict__ k1,
                       const float* __restrict__ k2, const float* __restrict__ k3)
{
    const size_t n = (size_t)36*16384;
    for (size_t i = (size_t)blockIdx.x*blockDim.x + threadIdx.x; i < n;
         i += (size_t)gridDim.x*blockDim.x){
        int z = (int)(i >> 14), rem = (int)(i & 16383);
        const float* sp = (z < 9)? k0 : (z < 18)? k1 : (z < 27)? k2 : k3;
        float v = sp[(size_t)(z % 9)*16384 + rem];
        __nv_bfloat16 hv = __float2bfloat16(v);
        g_wh[i] = hv;
        g_wl[i] = __float2bfloat16(v - __bfloat162float(hv));
    }
}

// ---------------------------------------------------------------------------
// Transposes
// ---------------------------------------------------------------------------
__global__ void t_in(const float* __restrict__ x)
{
    __shared__ float t[32][33];
    const int bh = blockIdx.z, b = bh>>7, hh = bh&127;
    const int w0 = blockIdx.x*32, c0 = blockIdx.y*32;
    const int tx = threadIdx.x, ty = threadIdx.y;
    const float* src = x + (((size_t)b*128 + c0)*128 + hh)*128 + w0;
    #pragma unroll
    for (int i=0;i<4;++i){ int cc = ty*4+i; t[cc][tx] = src[(size_t)cc*16384 + tx]; }
    __syncthreads();
    const size_t base = (((size_t)b*128 + hh)*128 + w0)*128 + c0;
    #pragma unroll
    for (int i=0;i<4;++i){
        int w = ty*4+i;
        float v = t[tx][w];
        size_t idx = base + (size_t)w*128 + tx;
        g_ws1[idx] = v;
        __nv_bfloat16 hv = __float2bfloat16(v);
        g_p1h[idx] = hv;
        g_p1l[idx] = __float2bfloat16(v - __bfloat162float(hv));
    }
}

__global__ void t_mid()
{
    const int b = blockIdx.z, hh = blockIdx.y;
    const int w = blockIdx.x*blockDim.y + threadIdx.y;
    const int c4 = threadIdx.x;
    const size_t si = (((size_t)b*128 + hh)*128 + w)*128 + c4*4;
    const size_t di = (((size_t)b*128 + w)*128 + hh)*128 + c4*4;
    float4 v = *(const float4*)(g_ws1 + si);
    *(float4*)(g_ws2 + di) = v;
    float a[4] = {v.x, v.y, v.z, v.w};
    #pragma unroll
    for (int i=0;i<4;++i){
        __nv_bfloat16 hv = __float2bfloat16(a[i]);
        g_p2h[di+i] = hv;
        g_p2l[di+i] = __float2bfloat16(a[i] - __bfloat162float(hv));
    }
}

__global__ void t_out(float* __restrict__ out)
{
    __shared__ float t[32][33];
    const int bh = blockIdx.z, b = bh>>7, hh = bh&127;
    const int w0 = blockIdx.x*32, c0 = blockIdx.y*32;
    const int tx = threadIdx.x, ty = threadIdx.y;
    const float* src = g_ws2 + (((size_t)b*128 + w0)*128 + hh)*128 + c0;
    #pragma unroll
    for (int i=0;i<4;++i){ int w = ty*4+i; t[w][tx] = src[(size_t)w*16384 + tx]; }
    __syncthreads();
    float* d = out + (((size_t)b*128 + c0)*128 + hh)*128 + w0;
    #pragma unroll
    for (int i=0;i<4;++i){ int cc = ty*4+i; d[(size_t)cc*16384 + tx] = t[tx][cc]; }
}

// ---------------------------------------------------------------------------
extern "C" void kernel_launch(void* const* d_in, const int* in_sizes, int n_in,
                              void* d_out, int out_size)
{
    const float* x    = (const float*)d_in[0];
    const float* k_td = (const float*)d_in[1];
    const float* k_dt = (const float*)d_in[2];
    const float* k_lr = (const float*)d_in[3];
    const float* k_rl = (const float*)d_in[4];
    float* out = (float*)d_out;

    static bool attr_done = false;
    if (!attr_done){
        cudaFuncSetAttribute(scan_kernel<0>, cudaFuncAttributeMaxDynamicSharedMemorySize, SMEM_BYTES);
        cudaFuncSetAttribute(scan_kernel<1>, cudaFuncAttributeMaxDynamicSharedMemorySize, SMEM_BYTES);
        attr_done = true;
    }

    const dim3 tb(32,8), tg(4,4,BB*HH);
    const dim3 sg(4,4,BB);   // 128 blocks: one co-resident wave

    zero_cnt<<<32,512>>>();
    prep_w<<<72,256>>>(k_td, k_dt, k_lr, k_rl);
    t_in<<<tg,tb>>>(x);

    scan_kernel<0><<<sg,256,SMEM_BYTES>>>(0, 0, 0);   // top-down
    scan_kernel<0><<<sg,256,SMEM_BYTES>>>(1, 1, 1);   // bottom-up

    t_mid<<<dim3(32,128,BB), dim3(32,4)>>>();

    scan_kernel<1><<<sg,256,SMEM_BYTES>>>(2, 0, 2);   // left-right
    scan_kernel<1><<<sg,256,SMEM_BYTES>>>(3, 1, 3);   // right-left

    t_out<<<tg,tb>>>(out);
}